// round 2
// baseline (speedup 1.0000x reference)
#include <cuda_runtime.h>
#include <cstdint>
#include <cstddef>

#define NN 50000
#define NE 600000
#define DD 128
#define NSTEP 5

// ---------------- device scratch (no allocations allowed) ----------------
static __device__ float g_agg[(size_t)4 * NN * DD];     // per-type aggregated h  [4][N][128]
static __device__ float g_cnt[4 * NN];                  // per-type in-degree (as float)
static __device__ float g_hbuf[(size_t)2 * NN * DD];    // ping-pong h
static __device__ float g_abuf[(size_t)NN * DD];        // aggregated+transformed "a"
static __device__ float g_gi[(size_t)NN * 3 * DD];      // a @ w_ih.T + b_ih
static __device__ float g_gh[(size_t)NN * 3 * DD];      // h @ w_hh.T + b_hh
static __device__ float g_wt1[128 * 512];               // repacked W_lin: [j][k*128+d]

// ---------------- f32x2 helpers (full-rate fp32 on sm_103a) ----------------
__device__ __forceinline__ unsigned long long pack2(float x) {
    unsigned long long r;
    asm("mov.b64 %0, {%1, %1};" : "=l"(r) : "f"(x));
    return r;
}
__device__ __forceinline__ void ffma2(unsigned long long& a, unsigned long long x,
                                      unsigned long long y) {
    asm("fma.rn.f32x2 %0, %1, %2, %0;" : "+l"(a) : "l"(x), "l"(y));
}
__device__ __forceinline__ float2 unpack2(unsigned long long v) {
    float2 r;
    asm("mov.b64 {%0, %1}, %2;" : "=f"(r.x), "=f"(r.y) : "l"(v));
    return r;
}

// ---------------- small utility kernels ----------------
__global__ void k_zero(float4* p, long n4) {
    long i = (long)blockIdx.x * blockDim.x + threadIdx.x;
    long stride = (long)gridDim.x * blockDim.x;
    float4 z = make_float4(0.f, 0.f, 0.f, 0.f);
    for (; i < n4; i += stride) p[i] = z;
}

__global__ void k_count(const int* __restrict__ dst, const int* __restrict__ et) {
    int e = blockIdx.x * blockDim.x + threadIdx.x;
    if (e < NE) atomicAdd(&g_cnt[(et[e] - 1) * NN + dst[e]], 1.0f);
}

// repack W_lin[k][j][d] -> g_wt1[j][k*128+d]  (rows contiguous over combined K=512)
__global__ void k_wt1(const float* __restrict__ Wlin) {
    int idx = blockIdx.x * blockDim.x + threadIdx.x;
    if (idx < 4 * 128 * 128) {
        int d = idx & 127;
        int j = (idx >> 7) & 127;
        int k = idx >> 14;
        g_wt1[j * 512 + k * 128 + d] = Wlin[(size_t)k * 16384 + j * 128 + d];
    }
}

// ---------------- edge aggregation: warp per edge, vector RED ----------------
__global__ void k_edge(const float* __restrict__ h, const int* __restrict__ src,
                       const int* __restrict__ dst, const int* __restrict__ et) {
    int gw = (blockIdx.x * blockDim.x + threadIdx.x) >> 5;
    int lane = threadIdx.x & 31;
    if (gw >= NE) return;
    int s = __ldg(&src[gw]);
    int d = __ldg(&dst[gw]);
    int k = __ldg(&et[gw]) - 1;
    float4 v = ((const float4*)h)[(size_t)s * 32 + lane];
    float* p = &g_agg[((size_t)k * NN + d) * DD + lane * 4];
    asm volatile("red.global.add.v4.f32 [%0], {%1,%2,%3,%4};"
                 :: "l"(p), "f"(v.x), "f"(v.y), "f"(v.z), "f"(v.w)
                 : "memory");
}

// ---------------- generic GEMM: C[i][j] = sum_k A[i][k]*W[j][k] (+bias[j]) (+cnt@blin) ----
// A layout: segment s = k/128, element A[s*aSeg + i*128 + (k%128)]  (row stride always 128)
// W row-major [Ncols][Kdim] (contiguous over k)
#define BM 64
#define BN 128
#define BK 16
#define ASD 68
#define WSD 132

__global__ __launch_bounds__(256)
void k_gemm(const float* __restrict__ A, size_t aSeg,
            const float* __restrict__ W, int Kdim,
            const float* __restrict__ bias,
            const float* __restrict__ cnt, const float* __restrict__ blin,
            float* __restrict__ C, int M, int Ncols) {
    __shared__ float As[BK * ASD];
    __shared__ float Ws[BK * WSD];
    int tid = threadIdx.x;
    int i0 = blockIdx.y * BM, j0 = blockIdx.x * BN;
    int arow = tid >> 2, ak = (tid & 3) * 4;       // A tile loader: 64 rows x 16 k
    int wj = tid >> 1, wk = (tid & 1) * 8;         // W tile loader: 128 j x 16 k
    int rowb = (tid >> 5) * 8;                     // compute: 8 rows / thread (as 4 pairs)
    int colb = (tid & 31) * 4;                     // 4 cols / thread

    unsigned long long acc[16];
#pragma unroll
    for (int i = 0; i < 16; i++) acc[i] = 0ULL;

    for (int kc = 0; kc < Kdim; kc += BK) {
        float4 av = make_float4(0.f, 0.f, 0.f, 0.f);
        int gr = i0 + arow;
        if (gr < M)
            av = *(const float4*)(A + (size_t)(kc >> 7) * aSeg + (size_t)gr * DD +
                                  (kc & 127) + ak);
        As[(ak + 0) * ASD + arow] = av.x;
        As[(ak + 1) * ASD + arow] = av.y;
        As[(ak + 2) * ASD + arow] = av.z;
        As[(ak + 3) * ASD + arow] = av.w;

        const float* wp = W + (size_t)(j0 + wj) * Kdim + kc + wk;
        float4 w0 = *(const float4*)wp;
        float4 w1 = *(const float4*)(wp + 4);
        Ws[(wk + 0) * WSD + wj] = w0.x;
        Ws[(wk + 1) * WSD + wj] = w0.y;
        Ws[(wk + 2) * WSD + wj] = w0.z;
        Ws[(wk + 3) * WSD + wj] = w0.w;
        Ws[(wk + 4) * WSD + wj] = w1.x;
        Ws[(wk + 5) * WSD + wj] = w1.y;
        Ws[(wk + 6) * WSD + wj] = w1.z;
        Ws[(wk + 7) * WSD + wj] = w1.w;
        __syncthreads();

#pragma unroll
        for (int kk = 0; kk < BK; ++kk) {
            const ulonglong2* ap2 = (const ulonglong2*)&As[kk * ASD + rowb];
            ulonglong2 a01 = ap2[0];
            ulonglong2 a23 = ap2[1];
            float4 b4 = *(const float4*)&Ws[kk * WSD + colb];
            unsigned long long b0 = pack2(b4.x), b1 = pack2(b4.y);
            unsigned long long b2 = pack2(b4.z), b3 = pack2(b4.w);
            ffma2(acc[0], a01.x, b0);  ffma2(acc[1], a01.x, b1);
            ffma2(acc[2], a01.x, b2);  ffma2(acc[3], a01.x, b3);
            ffma2(acc[4], a01.y, b0);  ffma2(acc[5], a01.y, b1);
            ffma2(acc[6], a01.y, b2);  ffma2(acc[7], a01.y, b3);
            ffma2(acc[8], a23.x, b0);  ffma2(acc[9], a23.x, b1);
            ffma2(acc[10], a23.x, b2); ffma2(acc[11], a23.x, b3);
            ffma2(acc[12], a23.y, b0); ffma2(acc[13], a23.y, b1);
            ffma2(acc[14], a23.y, b2); ffma2(acc[15], a23.y, b3);
        }
        __syncthreads();
    }

    float bv[4] = {0.f, 0.f, 0.f, 0.f};
    if (bias) {
#pragma unroll
        for (int c = 0; c < 4; c++) bv[c] = bias[j0 + colb + c];
    }
#pragma unroll
    for (int rp = 0; rp < 4; ++rp) {
        int gr = i0 + rowb + rp * 2;
        float2 v0 = unpack2(acc[rp * 4 + 0]);
        float2 v1 = unpack2(acc[rp * 4 + 1]);
        float2 v2 = unpack2(acc[rp * 4 + 2]);
        float2 v3 = unpack2(acc[rp * 4 + 3]);
        float4 e = make_float4(v0.x + bv[0], v1.x + bv[1], v2.x + bv[2], v3.x + bv[3]);
        float4 o = make_float4(v0.y + bv[0], v1.y + bv[1], v2.y + bv[2], v3.y + bv[3]);
        if (cnt) {
#pragma unroll
            for (int k4 = 0; k4 < 4; k4++) {
                float ce = (gr < M) ? cnt[k4 * NN + gr] : 0.f;
                float co = (gr + 1 < M) ? cnt[k4 * NN + gr + 1] : 0.f;
                const float* bl = blin + k4 * DD + j0 + colb;
                e.x += ce * bl[0]; e.y += ce * bl[1]; e.z += ce * bl[2]; e.w += ce * bl[3];
                o.x += co * bl[0]; o.y += co * bl[1]; o.z += co * bl[2]; o.w += co * bl[3];
            }
        }
        if (gr < M)     *(float4*)(C + (size_t)gr * Ncols + j0 + colb) = e;
        if (gr + 1 < M) *(float4*)(C + (size_t)(gr + 1) * Ncols + j0 + colb) = o;
    }
}

// ---------------- GRU elementwise ----------------
__device__ __forceinline__ float sigf(float x) { return 1.f / (1.f + __expf(-x)); }
__device__ __forceinline__ float gru1(float ir, float iz, float in_, float hr, float hz,
                                      float hn, float h) {
    float r = sigf(ir + hr);
    float z = sigf(iz + hz);
    float n = tanhf(in_ + r * hn);
    return (1.f - z) * n + z * h;
}

__global__ void k_gru(const float* __restrict__ gi, const float* __restrict__ gh,
                      const float* __restrict__ h, float* __restrict__ hout) {
    int idx = blockIdx.x * blockDim.x + threadIdx.x;
    if (idx >= NN * 32) return;
    int i = idx >> 5, c = idx & 31;
    const float4* gi4 = (const float4*)gi;
    const float4* gh4 = (const float4*)gh;
    float4 ir = gi4[(size_t)i * 96 + c];
    float4 iz = gi4[(size_t)i * 96 + 32 + c];
    float4 in_ = gi4[(size_t)i * 96 + 64 + c];
    float4 hr = gh4[(size_t)i * 96 + c];
    float4 hz = gh4[(size_t)i * 96 + 32 + c];
    float4 hn = gh4[(size_t)i * 96 + 64 + c];
    float4 hv = ((const float4*)h)[idx];
    float4 out;
    out.x = gru1(ir.x, iz.x, in_.x, hr.x, hz.x, hn.x, hv.x);
    out.y = gru1(ir.y, iz.y, in_.y, hr.y, hz.y, hn.y, hv.y);
    out.z = gru1(ir.z, iz.z, in_.z, hr.z, hz.z, hn.z, hv.z);
    out.w = gru1(ir.w, iz.w, in_.w, hr.w, hz.w, hn.w, hv.w);
    ((float4*)hout)[idx] = out;
}

// ---------------- launch ----------------
extern "C" void kernel_launch(void* const* d_in, const int* in_sizes, int n_in,
                              void* d_out, int out_size) {
    const float* h0 = (const float*)d_in[0];
    const int* src = (const int*)d_in[1];
    const int* dst = (const int*)d_in[2];
    const int* et = (const int*)d_in[3];
    const float* Wlin = (const float*)d_in[4];
    const float* blin = (const float*)d_in[5];
    const float* wih = (const float*)d_in[6];
    const float* whh = (const float*)d_in[7];
    const float* bih = (const float*)d_in[8];
    const float* bhh = (const float*)d_in[9];
    float* out = (float*)d_out;

    float *agg, *cnt, *hb, *ab, *gi, *gh, *wt1;
    cudaGetSymbolAddress((void**)&agg, g_agg);
    cudaGetSymbolAddress((void**)&cnt, g_cnt);
    cudaGetSymbolAddress((void**)&hb, g_hbuf);
    cudaGetSymbolAddress((void**)&ab, g_abuf);
    cudaGetSymbolAddress((void**)&gi, g_gi);
    cudaGetSymbolAddress((void**)&gh, g_gh);
    cudaGetSymbolAddress((void**)&wt1, g_wt1);

    // graph-constant precompute (cheap; runs every call for determinism)
    k_zero<<<64, 256>>>((float4*)cnt, (long)(4 * NN / 4));
    k_count<<<(NE + 255) / 256, 256>>>(dst, et);
    k_wt1<<<(4 * 128 * 128) / 256, 256>>>(Wlin);

    const float* hin = h0;
    for (int s = 0; s < NSTEP; s++) {
        float* hout = (s == NSTEP - 1) ? out : hb + (size_t)(s & 1) * NN * DD;

        k_zero<<<4096, 256>>>((float4*)agg, (long)((size_t)4 * NN * DD / 4));
        k_edge<<<NE * 32 / 256, 256>>>(hin, src, dst, et);

        dim3 g1(1, (NN + BM - 1) / BM);
        k_gemm<<<g1, 256>>>(agg, (size_t)NN * DD, wt1, 512, nullptr, cnt, blin, ab, NN, 128);

        dim3 g2(3, (NN + BM - 1) / BM);
        k_gemm<<<g2, 256>>>(ab, 0, wih, 128, bih, nullptr, nullptr, gi, NN, 384);
        k_gemm<<<g2, 256>>>(hin, 0, whh, 128, bhh, nullptr, nullptr, gh, NN, 384);

        k_gru<<<(NN * 32 + 255) / 256, 256>>>(gi, gh, hin, hout);
        hin = hout;
    }
}

// round 5
// speedup vs baseline: 1.3726x; 1.3726x over previous
#include <cuda_runtime.h>
#include <cuda_bf16.h>
#include <cstdint>
#include <cstddef>

#define NN 50000
#define NE 600000
#define DD 128
#define NSTEP 5
#define MT 391   // ceil(NN/128)

// ---------------- device scratch ----------------
static __device__ float g_agg[(size_t)4 * NN * DD];
static __device__ float g_cnt[4 * NN];
static __device__ float g_hbuf[(size_t)2 * NN * DD];
static __device__ float g_gh[(size_t)NN * 384];
static __device__ float g_gi[(size_t)NN * 384];
static __device__ __align__(16) __nv_bfloat16 g_wc_hi[384 * 512];
static __device__ __align__(16) __nv_bfloat16 g_wc_lo[384 * 512];
static __device__ __align__(16) __nv_bfloat16 g_whh_hi[384 * 128];
static __device__ __align__(16) __nv_bfloat16 g_whh_lo[384 * 128];
static __device__ float g_blinw[4 * 384];

// ---------------- helpers ----------------
__device__ __forceinline__ uint32_t s2u(const void* p) {
    uint32_t a;
    asm("{ .reg .u64 t; cvta.to.shared.u64 t, %1; cvt.u32.u64 %0, t; }" : "=r"(a) : "l"(p));
    return a;
}
__device__ __forceinline__ void cpa16(uint32_t dst, const void* src) {
    asm volatile("cp.async.cg.shared.global [%0], [%1], 16;" :: "r"(dst), "l"(src));
}
__device__ __forceinline__ void ldmx4(uint32_t* r, uint32_t addr) {
    asm volatile("ldmatrix.sync.aligned.m8n8.x4.shared.b16 {%0,%1,%2,%3}, [%4];"
                 : "=r"(r[0]), "=r"(r[1]), "=r"(r[2]), "=r"(r[3]) : "r"(addr));
}
__device__ __forceinline__ void mma16816(float* d, const uint32_t* a, const uint32_t* b) {
    asm volatile(
        "mma.sync.aligned.m16n8k16.row.col.f32.bf16.bf16.f32 "
        "{%0,%1,%2,%3}, {%4,%5,%6,%7}, {%8,%9}, {%0,%1,%2,%3};"
        : "+f"(d[0]), "+f"(d[1]), "+f"(d[2]), "+f"(d[3])
        : "r"(a[0]), "r"(a[1]), "r"(a[2]), "r"(a[3]), "r"(b[0]), "r"(b[1]));
}

// ---------------- small utility kernels ----------------
__global__ void k_zero(float4* p, long n4) {
    long i = (long)blockIdx.x * blockDim.x + threadIdx.x;
    long stride = (long)gridDim.x * blockDim.x;
    float4 z = make_float4(0.f, 0.f, 0.f, 0.f);
    for (; i < n4; i += stride) p[i] = z;
}

__global__ void k_count(const int* __restrict__ dst, const int* __restrict__ et) {
    int e = blockIdx.x * blockDim.x + threadIdx.x;
    if (e < NE) atomicAdd(&g_cnt[(et[e] - 1) * NN + dst[e]], 1.0f);
}

// Wc[j, k*128+d] = sum_d2 wih[j,d2] * Wlin[k][d2][d]; split to bf16 hi/lo
__global__ void k_wc(const float* __restrict__ wih, const float* __restrict__ Wlin) {
    int idx = blockIdx.x * blockDim.x + threadIdx.x;
    if (idx >= 384 * 512) return;
    int j = idx >> 9, kk = idx & 511, k = kk >> 7, d = kk & 127;
    const float* wr = wih + j * 128;
    const float* wl = Wlin + (size_t)k * 16384 + d;
    float s = 0.f;
#pragma unroll 8
    for (int d2 = 0; d2 < 128; d2++) s += wr[d2] * wl[(size_t)d2 * 128];
    __nv_bfloat16 h = __float2bfloat16(s);
    g_wc_hi[idx] = h;
    g_wc_lo[idx] = __float2bfloat16(s - __bfloat162float(h));
}

__global__ void k_whhcvt(const float* __restrict__ whh) {
    int idx = blockIdx.x * blockDim.x + threadIdx.x;
    if (idx < 384 * 128) {
        float x = whh[idx];
        __nv_bfloat16 h = __float2bfloat16(x);
        g_whh_hi[idx] = h;
        g_whh_lo[idx] = __float2bfloat16(x - __bfloat162float(h));
    }
}

__global__ void k_blinw(const float* __restrict__ blin, const float* __restrict__ wih) {
    int idx = blockIdx.x * blockDim.x + threadIdx.x;
    if (idx < 4 * 384) {
        int k = idx / 384, j = idx % 384;
        float s = 0.f;
        for (int d = 0; d < 128; d++) s += blin[k * 128 + d] * wih[j * 128 + d];
        g_blinw[idx] = s;
    }
}

// ---------------- edge aggregation: warp per edge, vector RED ----------------
__global__ void k_edge(const float* __restrict__ h, const int* __restrict__ src,
                       const int* __restrict__ dst, const int* __restrict__ et) {
    int gw = (blockIdx.x * blockDim.x + threadIdx.x) >> 5;
    int lane = threadIdx.x & 31;
    if (gw >= NE) return;
    int s = __ldg(&src[gw]);
    int d = __ldg(&dst[gw]);
    int k = __ldg(&et[gw]) - 1;
    float4 v = ((const float4*)h)[(size_t)s * 32 + lane];
    float* p = &g_agg[((size_t)k * NN + d) * DD + lane * 4];
    asm volatile("red.global.add.v4.f32 [%0], {%1,%2,%3,%4};"
                 :: "l"(p), "f"(v.x), "f"(v.y), "f"(v.z), "f"(v.w) : "memory");
}

// ---------------- mma.sync bf16 hi/lo GEMM: C[i0..+128, j0..+128] = A@B^T ----
// A fp32, segmented layout (seg = k/128, elem A[seg*aSeg + i*128 + k%128])
// B bf16 hi/lo, row-major [384][Kdim]. C fp32 [rows][384].
#define KC 64
#define ASTB 144                 // smem row stride in BYTES (72 bf16)
#define STG_A_H 0
#define STG_A_L 18432
#define STG_B_H 36864
#define STG_B_L 55296
#define STG_SZ 73728
#define SMEM_SZ (2 * STG_SZ)

__global__ __launch_bounds__(256)
void k_gemm(const float* __restrict__ A, size_t aSeg, int Kdim,
            const __nv_bfloat16* __restrict__ Bhi, const __nv_bfloat16* __restrict__ Blo,
            float* __restrict__ Cout) {
    extern __shared__ char sm[];
    uint32_t smb = s2u(sm);
    int tid = threadIdx.x, wid = tid >> 5, lane = tid & 31;
    int i0 = blockIdx.y * 128, j0 = blockIdx.x * 128;
    int wm = (wid & 1) * 64, wn = (wid >> 1) * 32;

    int aRow = tid >> 3, aKg = tid & 7;   // per-iter base (1024 items / 256 thr)
    float4 av0[4], av1[4];

    float acc[4][4][4];
#pragma unroll
    for (int a = 0; a < 4; a++)
#pragma unroll
        for (int b = 0; b < 4; b++)
#pragma unroll
            for (int c = 0; c < 4; c++) acc[a][b][c] = 0.f;

    int nCh = Kdim >> 6;

    // ---- stage loaders ----
#define LDG_A(ch)                                                                  \
    {                                                                              \
        int kc = (ch) * KC;                                                        \
        const float* ab = A + (size_t)(kc >> 7) * aSeg + (kc & 127);               \
        _Pragma("unroll") for (int it = 0; it < 4; it++) {                         \
            int row = aRow + it * 32;                                              \
            int gr = i0 + row;                                                     \
            if (gr < NN) {                                                         \
                const float* p = ab + (size_t)gr * DD + aKg * 8;                   \
                av0[it] = *(const float4*)p;                                       \
                av1[it] = *(const float4*)(p + 4);                                 \
            } else {                                                               \
                av0[it] = make_float4(0, 0, 0, 0);                                 \
                av1[it] = av0[it];                                                 \
            }                                                                      \
        }                                                                          \
    }

#define STS_A(buf)                                                                 \
    {                                                                              \
        uint32_t sb = smb + (buf) * STG_SZ;                                        \
        _Pragma("unroll") for (int it = 0; it < 4; it++) {                         \
            int row = aRow + it * 32;                                              \
            float f[8] = {av0[it].x, av0[it].y, av0[it].z, av0[it].w,              \
                          av1[it].x, av1[it].y, av1[it].z, av1[it].w};             \
            union { __nv_bfloat16 b[8]; uint4 u; } uh, ul;                         \
            _Pragma("unroll") for (int i = 0; i < 8; i++) {                        \
                __nv_bfloat16 hv = __float2bfloat16(f[i]);                         \
                uh.b[i] = hv;                                                      \
                ul.b[i] = __float2bfloat16(f[i] - __bfloat162float(hv));           \
            }                                                                      \
            uint32_t off = (uint32_t)row * ASTB + aKg * 16;                        \
            *(uint4*)(sm + (buf) * STG_SZ + STG_A_H + off) = uh.u;                 \
            *(uint4*)(sm + (buf) * STG_SZ + STG_A_L + off) = ul.u;                 \
        }                                                                          \
        (void)sb;                                                                  \
    }

#define CP_B(ch, buf)                                                              \
    {                                                                              \
        int kc = (ch) * KC;                                                        \
        uint32_t sb = smb + (buf) * STG_SZ;                                        \
        _Pragma("unroll") for (int it = 0; it < 4; it++) {                         \
            int row = aRow + it * 32;                                              \
            uint32_t off = (uint32_t)row * ASTB + aKg * 16;                        \
            const __nv_bfloat16* sh = Bhi + (size_t)(j0 + row) * Kdim + kc + aKg * 8; \
            const __nv_bfloat16* sl = Blo + (size_t)(j0 + row) * Kdim + kc + aKg * 8; \
            cpa16(sb + STG_B_H + off, sh);                                         \
            cpa16(sb + STG_B_L + off, sl);                                         \
        }                                                                          \
        asm volatile("cp.async.commit_group;");                                    \
    }

    // ---- prologue ----
    LDG_A(0);
    CP_B(0, 0);
    STS_A(0);
    asm volatile("cp.async.wait_group 0;");
    __syncthreads();

    // per-thread ldmatrix base addresses (stage-relative)
    uint32_t aOffH = STG_A_H + (uint32_t)(wm + (lane & 15)) * ASTB + (lane >> 4) * 16;
    uint32_t aOffL = aOffH + (STG_A_L - STG_A_H);
    uint32_t bRow = (uint32_t)(wn + (lane & 7) + ((lane >> 4) << 3));
    uint32_t bOffH = STG_B_H + bRow * ASTB + ((lane >> 3) & 1) * 16;
    uint32_t bOffL = bOffH + (STG_B_L - STG_B_H);

    for (int ch = 0; ch < nCh; ch++) {
        int buf = ch & 1;
        bool more = (ch + 1 < nCh);
        if (more) {
            LDG_A(ch + 1);
            CP_B(ch + 1, buf ^ 1);
        }
        uint32_t sb = smb + buf * STG_SZ;
#pragma unroll
        for (int ks = 0; ks < 4; ks++) {
            uint32_t ah[4][4], al[4][4];
#pragma unroll
            for (int mt = 0; mt < 4; mt++) {
                ldmx4(ah[mt], sb + aOffH + mt * (16 * ASTB) + ks * 32);
                ldmx4(al[mt], sb + aOffL + mt * (16 * ASTB) + ks * 32);
            }
            uint32_t bh[4][2], bl[4][2];
#pragma unroll
            for (int ntp = 0; ntp < 2; ntp++) {
                uint32_t t4[4];
                ldmx4(t4, sb + bOffH + ntp * (16 * ASTB) + ks * 32);
                bh[2 * ntp][0] = t4[0]; bh[2 * ntp][1] = t4[1];
                bh[2 * ntp + 1][0] = t4[2]; bh[2 * ntp + 1][1] = t4[3];
                ldmx4(t4, sb + bOffL + ntp * (16 * ASTB) + ks * 32);
                bl[2 * ntp][0] = t4[0]; bl[2 * ntp][1] = t4[1];
                bl[2 * ntp + 1][0] = t4[2]; bl[2 * ntp + 1][1] = t4[3];
            }
#pragma unroll
            for (int mt = 0; mt < 4; mt++)
#pragma unroll
                for (int nt = 0; nt < 4; nt++) {
                    mma16816(acc[mt][nt], ah[mt], bh[nt]);
                    mma16816(acc[mt][nt], ah[mt], bl[nt]);
                    mma16816(acc[mt][nt], al[mt], bh[nt]);
                }
        }
        if (more) {
            STS_A(buf ^ 1);
            asm volatile("cp.async.wait_group 0;");
            __syncthreads();
        }
    }

    // ---- epilogue ----
    int g = lane >> 2, tg = lane & 3;
#pragma unroll
    for (int mt = 0; mt < 4; mt++) {
        int r0 = i0 + wm + mt * 16 + g;
#pragma unroll
        for (int nt = 0; nt < 4; nt++) {
            int col = j0 + wn + nt * 8 + tg * 2;
            if (r0 < NN)
                *(float2*)(Cout + (size_t)r0 * 384 + col) =
                    make_float2(acc[mt][nt][0], acc[mt][nt][1]);
            if (r0 + 8 < NN)
                *(float2*)(Cout + (size_t)(r0 + 8) * 384 + col) =
                    make_float2(acc[mt][nt][2], acc[mt][nt][3]);
        }
    }
}

// ---------------- fused GRU + bias fold + agg zeroing ----------------
__device__ __forceinline__ float sigf(float x) { return 1.f / (1.f + __expf(-x)); }

__global__ void k_gru(const float* __restrict__ gi, const float* __restrict__ gh,
                      const float* __restrict__ hin, const float* __restrict__ cnt,
                      const float* __restrict__ blw, const float* __restrict__ bih,
                      const float* __restrict__ bhh, float* __restrict__ hout,
                      float* __restrict__ agg) {
    int idx = blockIdx.x * blockDim.x + threadIdx.x;
    if (idx >= NN * 32) return;
    int i = idx >> 5, c = idx & 31, j = c * 4;
    const float* gir_ = gi + (size_t)i * 384;
    const float* ghr_ = gh + (size_t)i * 384;
    float4 gir = *(const float4*)(gir_ + j);
    float4 giz = *(const float4*)(gir_ + 128 + j);
    float4 gin = *(const float4*)(gir_ + 256 + j);
    float4 ghr = *(const float4*)(ghr_ + j);
    float4 ghz = *(const float4*)(ghr_ + 128 + j);
    float4 ghn = *(const float4*)(ghr_ + 256 + j);
    float4 hv = *(const float4*)(hin + (size_t)i * DD + j);
    float cn[4] = {cnt[i], cnt[NN + i], cnt[2 * NN + i], cnt[3 * NN + i]};
    float gia[4] = {gir.x, gir.y, gir.z, gir.w};
    float gib[4] = {giz.x, giz.y, giz.z, giz.w};
    float gic[4] = {gin.x, gin.y, gin.z, gin.w};
    float gha[4] = {ghr.x, ghr.y, ghr.z, ghr.w};
    float ghb[4] = {ghz.x, ghz.y, ghz.z, ghz.w};
    float ghc[4] = {ghn.x, ghn.y, ghn.z, ghn.w};
    float hh[4] = {hv.x, hv.y, hv.z, hv.w};
    float o[4];
#pragma unroll
    for (int e = 0; e < 4; e++) {
        int jj = j + e;
        float cr = 0.f, cz = 0.f, cw = 0.f;
#pragma unroll
        for (int k = 0; k < 4; k++) {
            cr += cn[k] * blw[k * 384 + jj];
            cz += cn[k] * blw[k * 384 + 128 + jj];
            cw += cn[k] * blw[k * 384 + 256 + jj];
        }
        float r = sigf(gia[e] + gha[e] + bih[jj] + bhh[jj] + cr);
        float z = sigf(gib[e] + ghb[e] + bih[128 + jj] + bhh[128 + jj] + cz);
        float hn = ghc[e] + bhh[256 + jj];
        float n = tanhf(gic[e] + bih[256 + jj] + cw + r * hn);
        o[e] = (1.f - z) * n + z * hh[e];
    }
    *(float4*)(hout + (size_t)i * DD + j) = make_float4(o[0], o[1], o[2], o[3]);
    float4 zz = make_float4(0, 0, 0, 0);
#pragma unroll
    for (int k = 0; k < 4; k++)
        ((float4*)(agg + ((size_t)k * NN + i) * DD))[c] = zz;
}

// ---------------- launch ----------------
extern "C" void kernel_launch(void* const* d_in, const int* in_sizes, int n_in,
                              void* d_out, int out_size) {
    const float* h0 = (const float*)d_in[0];
    const int* src = (const int*)d_in[1];
    const int* dst = (const int*)d_in[2];
    const int* et = (const int*)d_in[3];
    const float* Wlin = (const float*)d_in[4];
    const float* blin = (const float*)d_in[5];
    const float* wih = (const float*)d_in[6];
    const float* whh = (const float*)d_in[7];
    const float* bih = (const float*)d_in[8];
    const float* bhh = (const float*)d_in[9];
    float* out = (float*)d_out;

    float *agg, *cnt, *hb, *ghb, *gib, *blw;
    __nv_bfloat16 *wchi, *wclo, *whi, *wlo;
    cudaGetSymbolAddress((void**)&agg, g_agg);
    cudaGetSymbolAddress((void**)&cnt, g_cnt);
    cudaGetSymbolAddress((void**)&hb, g_hbuf);
    cudaGetSymbolAddress((void**)&ghb, g_gh);
    cudaGetSymbolAddress((void**)&gib, g_gi);
    cudaGetSymbolAddress((void**)&blw, g_blinw);
    cudaGetSymbolAddress((void**)&wchi, g_wc_hi);
    cudaGetSymbolAddress((void**)&wclo, g_wc_lo);
    cudaGetSymbolAddress((void**)&whi, g_whh_hi);
    cudaGetSymbolAddress((void**)&wlo, g_whh_lo);

    cudaFuncSetAttribute(k_gemm, cudaFuncAttributeMaxDynamicSharedMemorySize, SMEM_SZ);

    // per-launch precompute
    k_zero<<<64, 256>>>((float4*)cnt, (long)(4 * NN / 4));
    k_zero<<<4096, 256>>>((float4*)agg, (long)((size_t)4 * NN * DD / 4));
    k_count<<<(NE + 255) / 256, 256>>>(dst, et);
    k_wc<<<(384 * 512) / 256, 256>>>(wih, Wlin);
    k_whhcvt<<<(384 * 128 + 255) / 256, 256>>>(whh);
    k_blinw<<<6, 256>>>(blin, wih);

    dim3 gg(3, MT);
    const float* hin = h0;
    for (int s = 0; s < NSTEP; s++) {
        float* hout = (s == NSTEP - 1) ? out : hb + (size_t)(s & 1) * NN * DD;

        k_edge<<<NE * 32 / 256, 256>>>(hin, src, dst, et);

        // gh = hin @ whh^T   (bias folded into k_gru)
        k_gemm<<<gg, 256, SMEM_SZ>>>(hin, 0, 128, whi, wlo, ghb);
        // gi = aggcat @ Wc^T (bias folded into k_gru)
        k_gemm<<<gg, 256, SMEM_SZ>>>(agg, (size_t)NN * DD, 512, wchi, wclo, gib);
        // fused GRU -> hout; zero agg for next step
        k_gru<<<(NN * 32 + 255) / 256, 256>>>(gib, ghb, hin, cnt, blw, bih, bhh, hout, agg);
        hin = hout;
    }
}

// round 7
// speedup vs baseline: 1.4086x; 1.0262x over previous
#include <cuda_runtime.h>
#include <cuda_bf16.h>
#include <cstdint>
#include <cstddef>

#define NN 50000
#define NE 600000
#define DD 128
#define NSTEP 5
#define MT 391   // ceil(NN/128)

// ---------------- device scratch ----------------
static __device__ float g_agg[(size_t)4 * NN * DD];
static __device__ float g_cnt[4 * NN];
static __device__ float g_hbuf[(size_t)2 * NN * DD];
static __device__ float g_gc[(size_t)NN * 512];   // [rsum|zsum|i_n|h_n]
static __device__ __align__(16) __nv_bfloat16 g_wc_hi[512 * 640];
static __device__ __align__(16) __nv_bfloat16 g_wc_lo[512 * 640];
static __device__ float g_blinw[4 * 384];

// ---------------- helpers ----------------
__device__ __forceinline__ uint32_t s2u(const void* p) {
    uint32_t a;
    asm("{ .reg .u64 t; cvta.to.shared.u64 t, %1; cvt.u32.u64 %0, t; }" : "=r"(a) : "l"(p));
    return a;
}
__device__ __forceinline__ void cpa16(uint32_t dst, const void* src) {
    asm volatile("cp.async.cg.shared.global [%0], [%1], 16;" :: "r"(dst), "l"(src));
}
__device__ __forceinline__ void ldmx4(uint32_t* r, uint32_t addr) {
    asm volatile("ldmatrix.sync.aligned.m8n8.x4.shared.b16 {%0,%1,%2,%3}, [%4];"
                 : "=r"(r[0]), "=r"(r[1]), "=r"(r[2]), "=r"(r[3]) : "r"(addr));
}
__device__ __forceinline__ void mma16816(float* d, const uint32_t* a, const uint32_t* b) {
    asm volatile(
        "mma.sync.aligned.m16n8k16.row.col.f32.bf16.bf16.f32 "
        "{%0,%1,%2,%3}, {%4,%5,%6,%7}, {%8,%9}, {%0,%1,%2,%3};"
        : "+f"(d[0]), "+f"(d[1]), "+f"(d[2]), "+f"(d[3])
        : "r"(a[0]), "r"(a[1]), "r"(a[2]), "r"(a[3]), "r"(b[0]), "r"(b[1]));
}

// ---------------- precompute kernels ----------------
__global__ void k_zeroall() {
    long i = (long)blockIdx.x * blockDim.x + threadIdx.x;
    long stride = (long)gridDim.x * blockDim.x;
    float4 z = make_float4(0.f, 0.f, 0.f, 0.f);
    float4* a4 = (float4*)g_agg;
    for (long p = i; p < 6400000L; p += stride) a4[p] = z;
    if (i < 50000) ((float4*)g_cnt)[i] = z;
}

__global__ void k_count(const int* __restrict__ dst, const int* __restrict__ et) {
    int e = blockIdx.x * blockDim.x + threadIdx.x;
    if (e < NE) atomicAdd(&g_cnt[(et[e] - 1) * NN + dst[e]], 1.0f);
}

// Wcomb rows 0-383, cols 0-511: (wih @ Wlin_k)[j][d], bf16 hi/lo split
__global__ void k_prepA(const float* __restrict__ wih, const float* __restrict__ Wlin) {
    int idx = blockIdx.x * blockDim.x + threadIdx.x;
    if (idx >= 384 * 512) return;
    int j = idx >> 9, kk = idx & 511, kt = kk >> 7, d = kk & 127;
    const float* wr = wih + j * 128;
    const float* wl = Wlin + (size_t)kt * 16384 + d;
    float s = 0.f;
#pragma unroll 8
    for (int d2 = 0; d2 < 128; d2++) s += wr[d2] * wl[(size_t)d2 * 128];
    __nv_bfloat16 h = __float2bfloat16(s);
    g_wc_hi[(size_t)j * 640 + kk] = h;
    g_wc_lo[(size_t)j * 640 + kk] = __float2bfloat16(s - __bfloat162float(h));
}

// Wcomb whh blocks (cols 512-639) + blw
__global__ void k_prepB(const float* __restrict__ whh, const float* __restrict__ blin,
                        const float* __restrict__ wih) {
    int idx = blockIdx.x * blockDim.x + threadIdx.x;
    if (idx < 32768) {           // rows 0-255 (r,z) <- whh rows 0-255
        int j = idx >> 7, c = idx & 127;
        float x = whh[idx];
        __nv_bfloat16 h = __float2bfloat16(x);
        g_wc_hi[(size_t)j * 640 + 512 + c] = h;
        g_wc_lo[(size_t)j * 640 + 512 + c] = __float2bfloat16(x - __bfloat162float(h));
    } else if (idx < 49152) {    // rows 384-511 (h_n) <- whh rows 256-383
        int t = idx - 32768;
        int j = t >> 7, c = t & 127;
        float x = whh[(256 + j) * 128 + c];
        __nv_bfloat16 h = __float2bfloat16(x);
        g_wc_hi[(size_t)(384 + j) * 640 + 512 + c] = h;
        g_wc_lo[(size_t)(384 + j) * 640 + 512 + c] = __float2bfloat16(x - __bfloat162float(h));
    } else if (idx < 50688) {    // blw[k][j] = blin[k] . wih[j]
        int t = idx - 49152;
        int k = t / 384, j = t % 384;
        float s = 0.f;
        for (int d = 0; d < 128; d++) s += blin[k * 128 + d] * wih[j * 128 + d];
        g_blinw[k * 384 + j] = s;
    }
}

// ---------------- edge aggregation: warp per edge, vector RED ----------------
__global__ void k_edge(const float* __restrict__ h, const int* __restrict__ src,
                       const int* __restrict__ dst, const int* __restrict__ et) {
    int gw = (blockIdx.x * blockDim.x + threadIdx.x) >> 5;
    int lane = threadIdx.x & 31;
    if (gw >= NE) return;
    int s = __ldg(&src[gw]);
    int d = __ldg(&dst[gw]);
    int k = __ldg(&et[gw]) - 1;
    float4 v = ((const float4*)h)[(size_t)s * 32 + lane];
    float* p = &g_agg[((size_t)k * NN + d) * DD + lane * 4];
    asm volatile("red.global.add.v4.f32 [%0], {%1,%2,%3,%4};"
                 :: "l"(p), "f"(v.x), "f"(v.y), "f"(v.z), "f"(v.w) : "memory");
}

// ---------------- merged 3xBF16 GEMM ----------------
// C[i0..+128, j0..+128] = Acomb @ Wcomb^T, Acomb = [agg seg0..3 | hin] (K<=640)
// jt0,1 (r,z): K=[0,640); jt2 (i_n): K=[0,512); jt3 (h_n): K=[512,640)
#define KC 32
#define RSTR 80
#define A_HALF 10240
#define A_ST_SZ 20480
#define B_BASE 40960
#define B_ST_SZ 20480
#define SMEM_SZ 102400

__global__ __launch_bounds__(256, 2)
void k_gemm(const float* __restrict__ agg, const float* __restrict__ hin,
            const __nv_bfloat16* __restrict__ Whi, const __nv_bfloat16* __restrict__ Wlo,
            float* __restrict__ Cout) {
    extern __shared__ char sm[];
    uint32_t smb = s2u(sm);
    int tid = threadIdx.x, wid = tid >> 5, lane = tid & 31;
    int jt = blockIdx.x;
    int i0 = blockIdx.y * 128, j0 = jt * 128;
    int kstart = (jt == 3) ? 512 : 0;
    int nCh = (jt == 2) ? 16 : ((jt == 3) ? 4 : 20);
    int wm = (wid & 1) * 64, wn = (wid >> 1) * 32;
    int aRow = tid >> 1, aHalf = tid & 1;
    int gr0 = i0 + aRow;

    float acc[4][4][4];
#pragma unroll
    for (int a = 0; a < 4; a++)
#pragma unroll
        for (int b = 0; b < 4; b++)
#pragma unroll
            for (int c = 0; c < 4; c++) acc[a][b][c] = 0.f;

    float4 av[4];

#define LDG_A(ch)                                                                   \
    {                                                                               \
        int kc_ = kstart + (ch) * KC;                                               \
        int seg_ = kc_ >> 7;                                                        \
        const float* ab_ = (seg_ < 4) ? (agg + (size_t)seg_ * NN * DD) : hin;       \
        if (gr0 < NN) {                                                             \
            const float4* p_ =                                                      \
                (const float4*)(ab_ + (size_t)gr0 * DD + (kc_ & 127) + aHalf * 16); \
            av[0] = p_[0]; av[1] = p_[1]; av[2] = p_[2]; av[3] = p_[3];             \
        } else {                                                                    \
            av[0] = make_float4(0, 0, 0, 0);                                        \
            av[1] = av[0]; av[2] = av[0]; av[3] = av[0];                            \
        }                                                                           \
    }

#define STS_A(buf)                                                                  \
    {                                                                               \
        union { __nv_bfloat16 b[16]; uint4 u[2]; } uh_, ul_;                        \
        const float* f_ = (const float*)av;                                         \
        _Pragma("unroll") for (int i = 0; i < 16; i++) {                            \
            __nv_bfloat16 hv_ = __float2bfloat16(f_[i]);                            \
            uh_.b[i] = hv_;                                                         \
            ul_.b[i] = __float2bfloat16(f_[i] - __bfloat162float(hv_));             \
        }                                                                           \
        uint32_t off_ = (uint32_t)(buf) * A_ST_SZ + aRow * RSTR + aHalf * 32;       \
        *(uint4*)(sm + off_) = uh_.u[0];                                            \
        *(uint4*)(sm + off_ + 16) = uh_.u[1];                                       \
        *(uint4*)(sm + off_ + A_HALF) = ul_.u[0];                                   \
        *(uint4*)(sm + off_ + A_HALF + 16) = ul_.u[1];                              \
    }

#define CP_B(ch, stg)                                                               \
    {                                                                               \
        int kc_ = kstart + (ch) * KC;                                               \
        uint32_t d_ = smb + B_BASE + (uint32_t)(stg) * B_ST_SZ + aRow * RSTR +      \
                      aHalf * 32;                                                   \
        const __nv_bfloat16* sh_ = Whi + (size_t)(j0 + aRow) * 640 + kc_ +          \
                                   aHalf * 16;                                      \
        const __nv_bfloat16* sl_ = Wlo + (size_t)(j0 + aRow) * 640 + kc_ +          \
                                   aHalf * 16;                                      \
        cpa16(d_, sh_);                                                             \
        cpa16(d_ + 16, sh_ + 8);                                                    \
        cpa16(d_ + A_HALF, sl_);                                                    \
        cpa16(d_ + A_HALF + 16, sl_ + 8);                                           \
        asm volatile("cp.async.commit_group;");                                     \
    }

    // ---- prologue ----
    CP_B(0, 0);
    CP_B(1, 1);
    LDG_A(0);
    STS_A(0);
    LDG_A(1);

    uint32_t aBase = (uint32_t)((wm + (lane & 15)) * RSTR + (lane >> 4) * 16);
    uint32_t bBase = B_BASE +
        (uint32_t)((wn + (lane & 7) + ((lane >> 4) << 3)) * RSTR + ((lane >> 3) & 1) * 16);

    for (int ch = 0; ch < nCh; ch++) {
        asm volatile("cp.async.wait_group 1;");
        __syncthreads();
        if (ch + 2 < nCh) {
            CP_B(ch + 2, (ch + 2) % 3);
        } else {
            asm volatile("cp.async.commit_group;");
        }
        uint32_t sa = smb + (uint32_t)(ch & 1) * A_ST_SZ + aBase;
        uint32_t sb = smb + (uint32_t)(ch % 3) * B_ST_SZ + bBase;
#pragma unroll
        for (int ks = 0; ks < 2; ks++) {
            uint32_t bh[4][2], bl[4][2], af[4][4];
#pragma unroll
            for (int np = 0; np < 2; np++) {
                uint32_t t4[4];
                ldmx4(t4, sb + np * (16 * RSTR) + ks * 32);
                bh[2 * np][0] = t4[0]; bh[2 * np][1] = t4[1];
                bh[2 * np + 1][0] = t4[2]; bh[2 * np + 1][1] = t4[3];
                ldmx4(t4, sb + A_HALF + np * (16 * RSTR) + ks * 32);
                bl[2 * np][0] = t4[0]; bl[2 * np][1] = t4[1];
                bl[2 * np + 1][0] = t4[2]; bl[2 * np + 1][1] = t4[3];
            }
#pragma unroll
            for (int mt = 0; mt < 4; mt++)
                ldmx4(af[mt], sa + mt * (16 * RSTR) + ks * 32);
#pragma unroll
            for (int mt = 0; mt < 4; mt++)
#pragma unroll
                for (int nt = 0; nt < 4; nt++) mma16816(acc[mt][nt], af[mt], bh[nt]);
#pragma unroll
            for (int mt = 0; mt < 4; mt++)
#pragma unroll
                for (int nt = 0; nt < 4; nt++) mma16816(acc[mt][nt], af[mt], bl[nt]);
#pragma unroll
            for (int mt = 0; mt < 4; mt++)
                ldmx4(af[mt], sa + A_HALF + mt * (16 * RSTR) + ks * 32);
#pragma unroll
            for (int mt = 0; mt < 4; mt++)
#pragma unroll
                for (int nt = 0; nt < 4; nt++) mma16816(acc[mt][nt], af[mt], bh[nt]);
        }
        if (ch + 1 < nCh) { STS_A((ch + 1) & 1); }
        if (ch + 2 < nCh) { LDG_A(ch + 2); }
    }

    // ---- epilogue ----
    int g = lane >> 2, tg = lane & 3;
#pragma unroll
    for (int mt = 0; mt < 4; mt++) {
        int r0 = i0 + wm + mt * 16 + g;
#pragma unroll
        for (int nt = 0; nt < 4; nt++) {
            int col = j0 + wn + nt * 8 + tg * 2;
            if (r0 < NN)
                *(float2*)(Cout + (size_t)r0 * 512 + col) =
                    make_float2(acc[mt][nt][0], acc[mt][nt][1]);
            if (r0 + 8 < NN)
                *(float2*)(Cout + (size_t)(r0 + 8) * 512 + col) =
                    make_float2(acc[mt][nt][2], acc[mt][nt][3]);
        }
    }
#undef LDG_A
#undef STS_A
#undef CP_B
}

// ---------------- fused GRU + bias fold + agg zeroing ----------------
__device__ __forceinline__ float sigf(float x) { return 1.f / (1.f + __expf(-x)); }

__global__ void k_gru(const float* __restrict__ gc, const float* __restrict__ hin,
                      const float* __restrict__ cnt, const float* __restrict__ blw,
                      const float* __restrict__ bih, const float* __restrict__ bhh,
                      float* __restrict__ hout, float* __restrict__ agg) {
    int idx = blockIdx.x * blockDim.x + threadIdx.x;
    if (idx >= NN * 32) return;
    int i = idx >> 5, c = idx & 31, j = c * 4;
    const float* C = gc + (size_t)i * 512;
    float4 rs4 = *(const float4*)(C + j);
    float4 zs4 = *(const float4*)(C + 128 + j);
    float4 in4 = *(const float4*)(C + 256 + j);
    float4 hn4 = *(const float4*)(C + 384 + j);
    float4 hv4 = *(const float4*)(hin + (size_t)i * DD + j);
    float cn[4] = {cnt[i], cnt[NN + i], cnt[2 * NN + i], cnt[3 * NN + i]};
    float RS[4] = {rs4.x, rs4.y, rs4.z, rs4.w};
    float ZS[4] = {zs4.x, zs4.y, zs4.z, zs4.w};
    float IN[4] = {in4.x, in4.y, in4.z, in4.w};
    float HN[4] = {hn4.x, hn4.y, hn4.z, hn4.w};
    float HH[4] = {hv4.x, hv4.y, hv4.z, hv4.w};
    float o[4];
#pragma unroll
    for (int e = 0; e < 4; e++) {
        int jj = j + e;
        float cr = 0.f, cz = 0.f, cw = 0.f;
#pragma unroll
        for (int k = 0; k < 4; k++) {
            cr += cn[k] * blw[k * 384 + jj];
            cz += cn[k] * blw[k * 384 + 128 + jj];
            cw += cn[k] * blw[k * 384 + 256 + jj];
        }
        float r = sigf(RS[e] + bih[jj] + bhh[jj] + cr);
        float z = sigf(ZS[e] + bih[128 + jj] + bhh[128 + jj] + cz);
        float n = tanhf(IN[e] + bih[256 + jj] + cw + r * (HN[e] + bhh[256 + jj]));
        o[e] = (1.f - z) * n + z * HH[e];
    }
    *(float4*)(hout + (size_t)i * DD + j) = make_float4(o[0], o[1], o[2], o[3]);
    float4 zz = make_float4(0, 0, 0, 0);
#pragma unroll
    for (int k = 0; k < 4; k++)
        ((float4*)(agg + ((size_t)k * NN + i) * DD))[c] = zz;
}

// ---------------- launch ----------------
extern "C" void kernel_launch(void* const* d_in, const int* in_sizes, int n_in,
                              void* d_out, int out_size) {
    const float* h0 = (const float*)d_in[0];
    const int* src = (const int*)d_in[1];
    const int* dst = (const int*)d_in[2];
    const int* et = (const int*)d_in[3];
    const float* Wlin = (const float*)d_in[4];
    const float* blin = (const float*)d_in[5];
    const float* wih = (const float*)d_in[6];
    const float* whh = (const float*)d_in[7];
    const float* bih = (const float*)d_in[8];
    const float* bhh = (const float*)d_in[9];
    float* out = (float*)d_out;

    float *agg, *cnt, *hb, *gcb, *blw;
    __nv_bfloat16 *whi, *wlo;
    cudaGetSymbolAddress((void**)&agg, g_agg);
    cudaGetSymbolAddress((void**)&cnt, g_cnt);
    cudaGetSymbolAddress((void**)&hb, g_hbuf);
    cudaGetSymbolAddress((void**)&gcb, g_gc);
    cudaGetSymbolAddress((void**)&blw, g_blinw);
    cudaGetSymbolAddress((void**)&whi, g_wc_hi);
    cudaGetSymbolAddress((void**)&wlo, g_wc_lo);

    cudaFuncSetAttribute(k_gemm, cudaFuncAttributeMaxDynamicSharedMemorySize, SMEM_SZ);

    // precompute (4 launches so the first k_gemm is launch #6 for ncu -s 5)
    k_zeroall<<<4096, 256>>>();
    k_count<<<(NE + 255) / 256, 256>>>(dst, et);
    k_prepA<<<(384 * 512) / 256, 256>>>(wih, Wlin);
    k_prepB<<<(50688 + 255) / 256, 256>>>(whh, blin, wih);

    dim3 gg(4, MT);
    const float* hin = h0;
    for (int s = 0; s < NSTEP; s++) {
        float* hout = (s == NSTEP - 1) ? out : hb + (size_t)(s & 1) * NN * DD;

        k_edge<<<NE * 32 / 256, 256>>>(hin, src, dst, et);
        k_gemm<<<gg, 256, SMEM_SZ>>>(agg, hin, whi, wlo, gcb);
        k_gru<<<(NN * 32 + 255) / 256, 256>>>(gcb, hin, cnt, blw, bih, bhh, hout, agg);
        hin = hout;
    }
}

// round 8
// speedup vs baseline: 1.5745x; 1.1178x over previous
#include <cuda_runtime.h>
#include <cuda_bf16.h>
#include <cstdint>
#include <cstddef>

#define NN 50000
#define NE 600000
#define DD 128
#define NSTEP 5
#define MT 391    // ceil(NN/128)
#define CSTR 128  // padded CSR stride (max in-degree headroom; E[deg]=12)

// ---------------- device scratch ----------------
static __device__ float g_agg[(size_t)4 * NN * DD];
static __device__ float g_cnt[4 * NN];
static __device__ int g_fillc[NN];
static __device__ uint32_t g_csr[(size_t)NN * CSTR];
static __device__ float g_hbuf[(size_t)2 * NN * DD];
static __device__ float g_gc[(size_t)NN * 512];   // [rsum|zsum|i_n|h_n]
static __device__ __align__(16) __nv_bfloat16 g_wc_hi[512 * 640];
static __device__ __align__(16) __nv_bfloat16 g_wc_lo[512 * 640];
static __device__ float g_blinw[4 * 384];

// ---------------- helpers ----------------
__device__ __forceinline__ uint32_t s2u(const void* p) {
    uint32_t a;
    asm("{ .reg .u64 t; cvta.to.shared.u64 t, %1; cvt.u32.u64 %0, t; }" : "=r"(a) : "l"(p));
    return a;
}
__device__ __forceinline__ void cpa16(uint32_t dst, const void* src) {
    asm volatile("cp.async.cg.shared.global [%0], [%1], 16;" :: "r"(dst), "l"(src));
}
__device__ __forceinline__ void ldmx4(uint32_t* r, uint32_t addr) {
    asm volatile("ldmatrix.sync.aligned.m8n8.x4.shared.b16 {%0,%1,%2,%3}, [%4];"
                 : "=r"(r[0]), "=r"(r[1]), "=r"(r[2]), "=r"(r[3]) : "r"(addr));
}
__device__ __forceinline__ void mma16816(float* d, const uint32_t* a, const uint32_t* b) {
    asm volatile(
        "mma.sync.aligned.m16n8k16.row.col.f32.bf16.bf16.f32 "
        "{%0,%1,%2,%3}, {%4,%5,%6,%7}, {%8,%9}, {%0,%1,%2,%3};"
        : "+f"(d[0]), "+f"(d[1]), "+f"(d[2]), "+f"(d[3])
        : "r"(a[0]), "r"(a[1]), "r"(a[2]), "r"(a[3]), "r"(b[0]), "r"(b[1]));
}

// ---------------- launch #1: zero counters ----------------
__global__ void k_zero0() {
    int i = blockIdx.x * blockDim.x + threadIdx.x;
    if (i < 4 * NN) g_cnt[i] = 0.f;
    if (i < NN) g_fillc[i] = 0;
}

// ---------------- launch #2: weight precompute (merged) ----------------
__global__ void k_prep(const float* __restrict__ wih, const float* __restrict__ Wlin,
                       const float* __restrict__ whh, const float* __restrict__ blin) {
    int idx = blockIdx.x * blockDim.x + threadIdx.x;
    if (idx < 196608) {  // Wcomb rows 0-383, cols 0-511: (wih @ Wlin_k), hi/lo
        int j = idx >> 9, kk = idx & 511, kt = kk >> 7, d = kk & 127;
        const float* wr = wih + j * 128;
        const float* wl = Wlin + (size_t)kt * 16384 + d;
        float s = 0.f;
#pragma unroll 8
        for (int d2 = 0; d2 < 128; d2++) s += wr[d2] * wl[(size_t)d2 * 128];
        __nv_bfloat16 h = __float2bfloat16(s);
        g_wc_hi[(size_t)j * 640 + kk] = h;
        g_wc_lo[(size_t)j * 640 + kk] = __float2bfloat16(s - __bfloat162float(h));
        return;
    }
    int t0 = idx - 196608;
    if (t0 < 32768) {            // rows 0-255 (r,z) cols 512-639 <- whh rows 0-255
        int j = t0 >> 7, c = t0 & 127;
        float x = whh[t0];
        __nv_bfloat16 h = __float2bfloat16(x);
        g_wc_hi[(size_t)j * 640 + 512 + c] = h;
        g_wc_lo[(size_t)j * 640 + 512 + c] = __float2bfloat16(x - __bfloat162float(h));
    } else if (t0 < 49152) {     // rows 384-511 (h_n) <- whh rows 256-383
        int t = t0 - 32768;
        int j = t >> 7, c = t & 127;
        float x = whh[(256 + j) * 128 + c];
        __nv_bfloat16 h = __float2bfloat16(x);
        g_wc_hi[(size_t)(384 + j) * 640 + 512 + c] = h;
        g_wc_lo[(size_t)(384 + j) * 640 + 512 + c] =
            __float2bfloat16(x - __bfloat162float(h));
    } else if (t0 < 50688) {     // blw[k][j] = blin[k] . wih[j]
        int t = t0 - 49152;
        int k = t / 384, j = t % 384;
        float s = 0.f;
        for (int d = 0; d < 128; d++) s += blin[k * 128 + d] * wih[j * 128 + d];
        g_blinw[k * 384 + j] = s;
    }
}

// ---------------- launch #3: CSR build + per-type degree counts ----------------
__global__ void k_build(const int* __restrict__ src, const int* __restrict__ dst,
                        const int* __restrict__ et) {
    int e = blockIdx.x * blockDim.x + threadIdx.x;
    if (e >= NE) return;
    int d = dst[e];
    int k = et[e] - 1;
    atomicAdd(&g_cnt[k * NN + d], 1.0f);
    int pos = atomicAdd(&g_fillc[d], 1);
    if (pos < CSTR)
        g_csr[(size_t)d * CSTR + pos] = (uint32_t)src[e] | ((uint32_t)k << 16);
}

// ---------------- per-step gather: warp per node, no atomics ----------------
__global__ __launch_bounds__(256)
void k_gather(const float* __restrict__ h) {
    int v = (blockIdx.x * blockDim.x + threadIdx.x) >> 5;
    int lane = threadIdx.x & 31;
    if (v >= NN) return;
    int deg = g_fillc[v];
    const uint32_t* row = &g_csr[(size_t)v * CSTR];
    const float4* h4 = (const float4*)h;
    float4 a0 = make_float4(0, 0, 0, 0), a1 = a0, a2 = a0, a3 = a0;
    for (int base = 0; base < deg; base += 32) {
        uint32_t pk = (base + lane < deg) ? row[base + lane] : 0u;
        int lim = min(32, deg - base);
        for (int j = 0; j < lim; j++) {
            uint32_t p = __shfl_sync(0xFFFFFFFFu, pk, j);
            int s = p & 0xFFFF;
            int k = p >> 16;
            float4 hv = h4[(size_t)s * 32 + lane];
            switch (k) {
                case 0: a0.x += hv.x; a0.y += hv.y; a0.z += hv.z; a0.w += hv.w; break;
                case 1: a1.x += hv.x; a1.y += hv.y; a1.z += hv.z; a1.w += hv.w; break;
                case 2: a2.x += hv.x; a2.y += hv.y; a2.z += hv.z; a2.w += hv.w; break;
                default: a3.x += hv.x; a3.y += hv.y; a3.z += hv.z; a3.w += hv.w; break;
            }
        }
    }
    float4* o = (float4*)(g_agg + (size_t)v * DD) + lane;
    o[0] = a0;
    o[(size_t)NN * 32] = a1;
    o[(size_t)2 * NN * 32] = a2;
    o[(size_t)3 * NN * 32] = a3;
}

// ---------------- merged 3xBF16 GEMM (unchanged from R6) ----------------
#define KC 32
#define RSTR 80
#define A_HALF 10240
#define A_ST_SZ 20480
#define B_BASE 40960
#define B_ST_SZ 20480
#define SMEM_SZ 102400

__global__ __launch_bounds__(256, 2)
void k_gemm(const float* __restrict__ agg, const float* __restrict__ hin,
            const __nv_bfloat16* __restrict__ Whi, const __nv_bfloat16* __restrict__ Wlo,
            float* __restrict__ Cout) {
    extern __shared__ char sm[];
    uint32_t smb = s2u(sm);
    int tid = threadIdx.x, wid = tid >> 5, lane = tid & 31;
    int jt = blockIdx.x;
    int i0 = blockIdx.y * 128, j0 = jt * 128;
    int kstart = (jt == 3) ? 512 : 0;
    int nCh = (jt == 2) ? 16 : ((jt == 3) ? 4 : 20);
    int wm = (wid & 1) * 64, wn = (wid >> 1) * 32;
    int aRow = tid >> 1, aHalf = tid & 1;
    int gr0 = i0 + aRow;

    float acc[4][4][4];
#pragma unroll
    for (int a = 0; a < 4; a++)
#pragma unroll
        for (int b = 0; b < 4; b++)
#pragma unroll
            for (int c = 0; c < 4; c++) acc[a][b][c] = 0.f;

    float4 av[4];

#define LDG_A(ch)                                                                   \
    {                                                                               \
        int kc_ = kstart + (ch) * KC;                                               \
        int seg_ = kc_ >> 7;                                                        \
        const float* ab_ = (seg_ < 4) ? (agg + (size_t)seg_ * NN * DD) : hin;       \
        if (gr0 < NN) {                                                             \
            const float4* p_ =                                                      \
                (const float4*)(ab_ + (size_t)gr0 * DD + (kc_ & 127) + aHalf * 16); \
            av[0] = p_[0]; av[1] = p_[1]; av[2] = p_[2]; av[3] = p_[3];             \
        } else {                                                                    \
            av[0] = make_float4(0, 0, 0, 0);                                        \
            av[1] = av[0]; av[2] = av[0]; av[3] = av[0];                            \
        }                                                                           \
    }

#define STS_A(buf)                                                                  \
    {                                                                               \
        union { __nv_bfloat16 b[16]; uint4 u[2]; } uh_, ul_;                        \
        const float* f_ = (const float*)av;                                         \
        _Pragma("unroll") for (int i = 0; i < 16; i++) {                            \
            __nv_bfloat16 hv_ = __float2bfloat16(f_[i]);                            \
            uh_.b[i] = hv_;                                                         \
            ul_.b[i] = __float2bfloat16(f_[i] - __bfloat162float(hv_));             \
        }                                                                           \
        uint32_t off_ = (uint32_t)(buf) * A_ST_SZ + aRow * RSTR + aHalf * 32;       \
        *(uint4*)(sm + off_) = uh_.u[0];                                            \
        *(uint4*)(sm + off_ + 16) = uh_.u[1];                                       \
        *(uint4*)(sm + off_ + A_HALF) = ul_.u[0];                                   \
        *(uint4*)(sm + off_ + A_HALF + 16) = ul_.u[1];                              \
    }

#define CP_B(ch, stg)                                                               \
    {                                                                               \
        int kc_ = kstart + (ch) * KC;                                               \
        uint32_t d_ = smb + B_BASE + (uint32_t)(stg) * B_ST_SZ + aRow * RSTR +      \
                      aHalf * 32;                                                   \
        const __nv_bfloat16* sh_ = Whi + (size_t)(j0 + aRow) * 640 + kc_ +          \
                                   aHalf * 16;                                      \
        const __nv_bfloat16* sl_ = Wlo + (size_t)(j0 + aRow) * 640 + kc_ +          \
                                   aHalf * 16;                                      \
        cpa16(d_, sh_);                                                             \
        cpa16(d_ + 16, sh_ + 8);                                                    \
        cpa16(d_ + A_HALF, sl_);                                                    \
        cpa16(d_ + A_HALF + 16, sl_ + 8);                                           \
        asm volatile("cp.async.commit_group;");                                     \
    }

    CP_B(0, 0);
    CP_B(1, 1);
    LDG_A(0);
    STS_A(0);
    LDG_A(1);

    uint32_t aBase = (uint32_t)((wm + (lane & 15)) * RSTR + (lane >> 4) * 16);
    uint32_t bBase = B_BASE +
        (uint32_t)((wn + (lane & 7) + ((lane >> 4) << 3)) * RSTR + ((lane >> 3) & 1) * 16);

    for (int ch = 0; ch < nCh; ch++) {
        asm volatile("cp.async.wait_group 1;");
        __syncthreads();
        if (ch + 2 < nCh) {
            CP_B(ch + 2, (ch + 2) % 3);
        } else {
            asm volatile("cp.async.commit_group;");
        }
        uint32_t sa = smb + (uint32_t)(ch & 1) * A_ST_SZ + aBase;
        uint32_t sb = smb + (uint32_t)(ch % 3) * B_ST_SZ + bBase;
#pragma unroll
        for (int ks = 0; ks < 2; ks++) {
            uint32_t bh[4][2], bl[4][2], af[4][4];
#pragma unroll
            for (int np = 0; np < 2; np++) {
                uint32_t t4[4];
                ldmx4(t4, sb + np * (16 * RSTR) + ks * 32);
                bh[2 * np][0] = t4[0]; bh[2 * np][1] = t4[1];
                bh[2 * np + 1][0] = t4[2]; bh[2 * np + 1][1] = t4[3];
                ldmx4(t4, sb + A_HALF + np * (16 * RSTR) + ks * 32);
                bl[2 * np][0] = t4[0]; bl[2 * np][1] = t4[1];
                bl[2 * np + 1][0] = t4[2]; bl[2 * np + 1][1] = t4[3];
            }
#pragma unroll
            for (int mt = 0; mt < 4; mt++)
                ldmx4(af[mt], sa + mt * (16 * RSTR) + ks * 32);
#pragma unroll
            for (int mt = 0; mt < 4; mt++)
#pragma unroll
                for (int nt = 0; nt < 4; nt++) mma16816(acc[mt][nt], af[mt], bh[nt]);
#pragma unroll
            for (int mt = 0; mt < 4; mt++)
#pragma unroll
                for (int nt = 0; nt < 4; nt++) mma16816(acc[mt][nt], af[mt], bl[nt]);
#pragma unroll
            for (int mt = 0; mt < 4; mt++)
                ldmx4(af[mt], sa + A_HALF + mt * (16 * RSTR) + ks * 32);
#pragma unroll
            for (int mt = 0; mt < 4; mt++)
#pragma unroll
                for (int nt = 0; nt < 4; nt++) mma16816(acc[mt][nt], af[mt], bh[nt]);
        }
        if (ch + 1 < nCh) { STS_A((ch + 1) & 1); }
        if (ch + 2 < nCh) { LDG_A(ch + 2); }
    }

    int g = lane >> 2, tg = lane & 3;
#pragma unroll
    for (int mt = 0; mt < 4; mt++) {
        int r0 = i0 + wm + mt * 16 + g;
#pragma unroll
        for (int nt = 0; nt < 4; nt++) {
            int col = j0 + wn + nt * 8 + tg * 2;
            if (r0 < NN)
                *(float2*)(Cout + (size_t)r0 * 512 + col) =
                    make_float2(acc[mt][nt][0], acc[mt][nt][1]);
            if (r0 + 8 < NN)
                *(float2*)(Cout + (size_t)(r0 + 8) * 512 + col) =
                    make_float2(acc[mt][nt][2], acc[mt][nt][3]);
        }
    }
#undef LDG_A
#undef STS_A
#undef CP_B
}

// ---------------- fused GRU + bias fold (no agg zeroing anymore) ----------------
__device__ __forceinline__ float sigf(float x) { return 1.f / (1.f + __expf(-x)); }

__global__ void k_gru(const float* __restrict__ gc, const float* __restrict__ hin,
                      const float* __restrict__ cnt, const float* __restrict__ blw,
                      const float* __restrict__ bih, const float* __restrict__ bhh,
                      float* __restrict__ hout) {
    int idx = blockIdx.x * blockDim.x + threadIdx.x;
    if (idx >= NN * 32) return;
    int i = idx >> 5, c = idx & 31, j = c * 4;
    const float* C = gc + (size_t)i * 512;
    float4 rs4 = *(const float4*)(C + j);
    float4 zs4 = *(const float4*)(C + 128 + j);
    float4 in4 = *(const float4*)(C + 256 + j);
    float4 hn4 = *(const float4*)(C + 384 + j);
    float4 hv4 = *(const float4*)(hin + (size_t)i * DD + j);
    float cn[4] = {cnt[i], cnt[NN + i], cnt[2 * NN + i], cnt[3 * NN + i]};
    float RS[4] = {rs4.x, rs4.y, rs4.z, rs4.w};
    float ZS[4] = {zs4.x, zs4.y, zs4.z, zs4.w};
    float IN[4] = {in4.x, in4.y, in4.z, in4.w};
    float HN[4] = {hn4.x, hn4.y, hn4.z, hn4.w};
    float HH[4] = {hv4.x, hv4.y, hv4.z, hv4.w};
    float o[4];
#pragma unroll
    for (int e = 0; e < 4; e++) {
        int jj = j + e;
        float cr = 0.f, cz = 0.f, cw = 0.f;
#pragma unroll
        for (int k = 0; k < 4; k++) {
            cr += cn[k] * blw[k * 384 + jj];
            cz += cn[k] * blw[k * 384 + 128 + jj];
            cw += cn[k] * blw[k * 384 + 256 + jj];
        }
        float r = sigf(RS[e] + bih[jj] + bhh[jj] + cr);
        float z = sigf(ZS[e] + bih[128 + jj] + bhh[128 + jj] + cz);
        float n = tanhf(IN[e] + bih[256 + jj] + cw + r * (HN[e] + bhh[256 + jj]));
        o[e] = (1.f - z) * n + z * HH[e];
    }
    *(float4*)(hout + (size_t)i * DD + j) = make_float4(o[0], o[1], o[2], o[3]);
}

// ---------------- launch ----------------
extern "C" void kernel_launch(void* const* d_in, const int* in_sizes, int n_in,
                              void* d_out, int out_size) {
    const float* h0 = (const float*)d_in[0];
    const int* src = (const int*)d_in[1];
    const int* dst = (const int*)d_in[2];
    const int* et = (const int*)d_in[3];
    const float* Wlin = (const float*)d_in[4];
    const float* blin = (const float*)d_in[5];
    const float* wih = (const float*)d_in[6];
    const float* whh = (const float*)d_in[7];
    const float* bih = (const float*)d_in[8];
    const float* bhh = (const float*)d_in[9];
    float* out = (float*)d_out;

    float *agg, *cnt, *hb, *gcb, *blw;
    __nv_bfloat16 *whi, *wlo;
    cudaGetSymbolAddress((void**)&agg, g_agg);
    cudaGetSymbolAddress((void**)&cnt, g_cnt);
    cudaGetSymbolAddress((void**)&hb, g_hbuf);
    cudaGetSymbolAddress((void**)&gcb, g_gc);
    cudaGetSymbolAddress((void**)&blw, g_blinw);
    cudaGetSymbolAddress((void**)&whi, g_wc_hi);
    cudaGetSymbolAddress((void**)&wlo, g_wc_lo);

    cudaFuncSetAttribute(k_gemm, cudaFuncAttributeMaxDynamicSharedMemorySize, SMEM_SZ);

    // launches 1-3 (ncu captures launch #4 = first k_gather)
    k_zero0<<<(4 * NN + 255) / 256, 256>>>();
    k_prep<<<(247296 + 255) / 256, 256>>>(wih, Wlin, whh, blin);
    k_build<<<(NE + 255) / 256, 256>>>(src, dst, et);

    dim3 gg(4, MT);
    const float* hin = h0;
    for (int s = 0; s < NSTEP; s++) {
        float* hout = (s == NSTEP - 1) ? out : hb + (size_t)(s & 1) * NN * DD;

        k_gather<<<(NN * 32 + 255) / 256, 256>>>(hin);
        k_gemm<<<gg, 256, SMEM_SZ>>>(agg, hin, whi, wlo, gcb);
        k_gru<<<(NN * 32 + 255) / 256, 256>>>(gcb, hin, cnt, blw, bih, bhh, hout);
        hin = hout;
    }
}